// round 11
// baseline (speedup 1.0000x reference)
#include <cuda_runtime.h>
#include <cuda_fp16.h>

// ---------------------------------------------------------------------------
// Problem constants
#define R_TOTAL   327680          // N*T*VN rows
#define BTOT      32768           // N*T graph items
#define NB        8               // items per block
#define ROWS      (NB*10)         // 80 rows per block = 5 m-tiles, NO padding
#define MT        5               // m-tiles
#define NBLK_STATS 2048
#define BN_EPS    1e-5f

// Scratch (allocation-free)
__device__ float g_psum[NBLK_STATS * 128];
__device__ float g_psq [NBLK_STATS * 128];
__device__ float g_scale[128];
__device__ float g_shift[128];
// Pre-permuted fp16 weights in m16n8k16 B-fragment order:
// [nt][kst(8)][lane(32)] -> uint2 {b0 = W[k0,k0+1][n], b1 = W[k0+8,k0+9][n]}
// q-part (nt 0..15) pre-scaled by 0.25 (the attention logit scale; exact pow2)
__device__ uint2 g_wqkv16[48 * 8 * 32];
__device__ uint2 g_wout16[16 * 8 * 32];

// ---------------------------------------------------------------------------
__device__ __forceinline__ unsigned pkh2(float a, float b) {
    __half2 h = __floats2half2_rn(a, b);
    return *(unsigned*)&h;
}
__device__ __forceinline__ __half2 u2h2(unsigned u) { return *(__half2*)&u; }

// fp32-accumulator fp16 mma
__device__ __forceinline__ void mma_f16(float& c0, float& c1, float& c2, float& c3,
                                        unsigned a0, unsigned a1, unsigned a2, unsigned a3,
                                        unsigned b0, unsigned b1) {
    asm volatile("mma.sync.aligned.m16n8k16.row.col.f32.f16.f16.f32 "
                 "{%0,%1,%2,%3}, {%4,%5,%6,%7}, {%8,%9}, {%0,%1,%2,%3};\n"
                 : "+f"(c0), "+f"(c1), "+f"(c2), "+f"(c3)
                 : "r"(a0), "r"(a1), "r"(a2), "r"(a3), "r"(b0), "r"(b1));
}

// fp16-accumulator fp16 mma (C/D packed half2 x2)
__device__ __forceinline__ void mma_f16acc(unsigned& c0, unsigned& c1,
                                           unsigned a0, unsigned a1, unsigned a2, unsigned a3,
                                           unsigned b0, unsigned b1) {
    asm volatile("mma.sync.aligned.m16n8k16.row.col.f16.f16.f16.f16 "
                 "{%0,%1}, {%2,%3,%4,%5}, {%6,%7}, {%0,%1};\n"
                 : "+r"(c0), "+r"(c1)
                 : "r"(a0), "r"(a1), "r"(a2), "r"(a3), "r"(b0), "r"(b1));
}

// packed fp32x2 ops (Blackwell FFMA2 — PTX-only)
#define FMA2(o, a, v) asm("fma.rn.f32x2 %0, %1, %2, %0;" : "+l"(o) : "l"(a), "l"(v))
#define MUL2(o, s)    asm("mul.rn.f32x2 %0, %0, %1;"     : "+l"(o) : "l"(s))
#define BCAST2(o, f)  asm("mov.b64 %0, {%1, %1};"        : "=l"(o) : "f"(f))
#define UNPK2(lo, hi, o) asm("mov.b64 {%0, %1}, %2;" : "=f"(lo), "=f"(hi) : "l"(o))

__device__ __forceinline__ float ex2f(float x) {
    float r;
    asm("ex2.approx.f32 %0, %1;" : "=f"(r) : "f"(x));
    return r;
}
__device__ __forceinline__ float rcpf(float x) {
    float r;
    asm("rcp.approx.f32 %0, %1;" : "=f"(r) : "f"(x));
    return r;
}

// half2 dot of 16 fp16 values (2x uint4), fp32 finish
__device__ __forceinline__ float hdot16(uint4 qa, uint4 qb, uint4 ka, uint4 kb) {
    __half2 s = __hmul2(u2h2(qa.x), u2h2(ka.x));
    s = __hfma2(u2h2(qa.y), u2h2(ka.y), s);
    s = __hfma2(u2h2(qa.z), u2h2(ka.z), s);
    s = __hfma2(u2h2(qa.w), u2h2(ka.w), s);
    s = __hfma2(u2h2(qb.x), u2h2(kb.x), s);
    s = __hfma2(u2h2(qb.y), u2h2(kb.y), s);
    s = __hfma2(u2h2(qb.z), u2h2(kb.z), s);
    s = __hfma2(u2h2(qb.w), u2h2(kb.w), s);
    float2 f = __half22float2(s);
    return f.x + f.y;
}

// ---------------------------------------------------------------------------
// Kernel 1: per-channel sum / sumsq partials (DRAM-bound, ~32us)
// ---------------------------------------------------------------------------
__global__ void __launch_bounds__(256) stats_kernel(const float4* __restrict__ x4) {
    __shared__ float s_sum[256][4];
    __shared__ float s_sq [256][4];
    const int tid  = threadIdx.x;
    const int lane = tid & 31;
    const int slot = tid >> 5;

    float4 sum = make_float4(0.f, 0.f, 0.f, 0.f);
    float4 sq  = make_float4(0.f, 0.f, 0.f, 0.f);

    int row = blockIdx.x * 8 + slot;
    const int stride = NBLK_STATS * 8;
    #pragma unroll 8
    for (int it = 0; it < R_TOTAL / stride; ++it) {
        float4 v = x4[(size_t)row * 32 + lane];
        sum.x += v.x; sum.y += v.y; sum.z += v.z; sum.w += v.w;
        sq.x += v.x * v.x; sq.y += v.y * v.y; sq.z += v.z * v.z; sq.w += v.w * v.w;
        row += stride;
    }
    s_sum[tid][0] = sum.x; s_sum[tid][1] = sum.y; s_sum[tid][2] = sum.z; s_sum[tid][3] = sum.w;
    s_sq [tid][0] = sq.x;  s_sq [tid][1] = sq.y;  s_sq [tid][2] = sq.z;  s_sq [tid][3] = sq.w;
    __syncthreads();
    for (int off = 128; off >= 32; off >>= 1) {
        if (tid < off) {
            #pragma unroll
            for (int j = 0; j < 4; ++j) {
                s_sum[tid][j] += s_sum[tid + off][j];
                s_sq [tid][j] += s_sq [tid + off][j];
            }
        }
        __syncthreads();
    }
    if (tid < 32) {
        #pragma unroll
        for (int j = 0; j < 4; ++j) {
            g_psum[blockIdx.x * 128 + tid * 4 + j] = s_sum[tid][j];
            g_psq [blockIdx.x * 128 + tid * 4 + j] = s_sq [tid][j];
        }
    }
}

// ---------------------------------------------------------------------------
// Kernel 2: merged weight permute (blocks 0..11) + BN finalize (block 12)
// ---------------------------------------------------------------------------
__global__ void __launch_bounds__(1024) prep_kernel(const float* __restrict__ gamma,
                                                    const float* __restrict__ beta,
                                                    const float* __restrict__ wqkv,
                                                    const float* __restrict__ wout) {
    if (blockIdx.x < 12) {
        int idx = blockIdx.x * 1024 + threadIdx.x;     // 0..12287
        {
            int lane = idx & 31;
            int kst  = (idx >> 5) & 7;
            int nt   = idx >> 8;                       // 0..47
            int tig = lane & 3, gid = lane >> 2;
            int k0 = kst * 16 + 2 * tig;
            int n  = nt * 8 + gid;
            float s = (nt < 16) ? 0.25f : 1.0f;        // fold logit scale into Wq
            uint2 v;
            v.x = pkh2(s * wqkv[k0 * 384 + n],       s * wqkv[(k0 + 1) * 384 + n]);
            v.y = pkh2(s * wqkv[(k0 + 8) * 384 + n], s * wqkv[(k0 + 9) * 384 + n]);
            g_wqkv16[idx] = v;
        }
        if (idx < 16 * 8 * 32) {
            int lane = idx & 31;
            int kst  = (idx >> 5) & 7;
            int nt   = idx >> 8;                       // 0..15
            int tig = lane & 3, gid = lane >> 2;
            int k0 = kst * 16 + 2 * tig;
            int n  = nt * 8 + gid;
            uint2 v;
            v.x = pkh2(wout[k0 * 128 + n],       wout[(k0 + 1) * 128 + n]);
            v.y = pkh2(wout[(k0 + 8) * 128 + n], wout[(k0 + 9) * 128 + n]);
            g_wout16[idx] = v;
        }
    } else {
        __shared__ float r_sum[1024];
        __shared__ float r_sq [1024];
        const int tid = threadIdx.x;
        const int c = tid & 127;
        const int s = tid >> 7;
        float sum = 0.f, sq = 0.f;
        #pragma unroll 8
        for (int b = s; b < NBLK_STATS; b += 8) {
            sum += g_psum[b * 128 + c];
            sq  += g_psq [b * 128 + c];
        }
        r_sum[tid] = sum;
        r_sq [tid] = sq;
        __syncthreads();
        if (tid < 128) {
            float S = 0.f, Q = 0.f;
            #pragma unroll
            for (int j = 0; j < 8; ++j) { S += r_sum[j * 128 + c]; Q += r_sq[j * 128 + c]; }
            const float inv_n = 1.0f / (float)R_TOTAL;
            float mean = S * inv_n;
            float var  = Q * inv_n - mean * mean;
            float sc   = gamma[c] * rsqrtf(var + BN_EPS);
            g_scale[c] = sc;
            g_shift[c] = beta[c] - mean * sc;
        }
    }
}

// ---------------------------------------------------------------------------
// Kernel 3: fused BN-normalize -> QKV (fp16 mma) -> attention -> out-proj
// 256 threads, 2 blocks/SM (R8/R10-verified structure) + LDG double-buffering
// smem: sy16 20KB | qh/kh fp16 21KB each | vv fp32 41KB | small 2KB = ~107KB
// ---------------------------------------------------------------------------
#define QH_BLK   168                        // per-pair q/k stride in halves
#define V_BLK    164                        // per-pair v stride in floats
#define SY_U32   (MT * 8 * 128)             // 5120
#define SMEM_FLOATS (SY_U32 + 2 * (64 * QH_BLK / 2) + 64 * V_BLK + 512)
#define SMEM_BYTES  (SMEM_FLOATS * 4)

__global__ void __launch_bounds__(256, 2)
main_kernel(const float* __restrict__ x,
            const float* __restrict__ b_out,
            const float* __restrict__ mask,
            float* __restrict__ out) {
    extern __shared__ float sm[];
    unsigned* sy16 = (unsigned*)sm;               // [mt][kst][lane^kst][4 regs]
    unsigned short* qh = (unsigned short*)(sm + SY_U32);
    unsigned short* kh = qh + 64 * QH_BLK;
    float* vv      = sm + SY_U32 + (64 * QH_BLK); // after qh+kh (2*168*64 halves)
    float* s_scale = vv + 64 * V_BLK;
    float* s_shift = s_scale + 128;
    float* s_mask  = s_shift + 128;               // mask * log2(e)
    float* s_bout  = s_mask + 128;

    const int tid  = threadIdx.x;
    const int lane = tid & 31;
    const int wrp  = tid >> 5;
    const int tig  = lane & 3;
    const int gid  = lane >> 2;
    const int row0 = blockIdx.x * ROWS;

    // P2 weight pointers + kst=0 preload issued BEFORE Phase 1 so the L2
    // latency hides behind P1's DRAM loads.
    const uint2* gqk = g_wqkv16 + (4 * wrp) * 8 * 32 + lane;
    const uint2* gv  = g_wqkv16 + (32 + 2 * wrp) * 8 * 32 + lane;
    uint2 bqk[2][4], bv[2][2];
    #pragma unroll
    for (int n = 0; n < 4; ++n) bqk[0][n] = __ldg(gqk + n * 8 * 32);
    #pragma unroll
    for (int n = 0; n < 2; ++n) bv[0][n]  = __ldg(gv  + n * 8 * 32);

    if (tid < 128) {
        s_scale[tid] = g_scale[tid];
        s_shift[tid] = g_shift[tid];
        s_bout [tid] = b_out[tid];
    }
    if (tid < 100) s_mask[tid] = mask[tid] * 1.44269504f;  // fold log2e for ex2
    __syncthreads();

    // ---- Phase 1: load + BN-normalize x into fp16 A-fragment sy (no pad) ---
    {
        const float4* x4  = (const float4*)x;
        const float4* sc4 = (const float4*)s_scale;
        const float4* sh4 = (const float4*)s_shift;
        #pragma unroll
        for (int f = tid; f < MT * 16 * 32; f += 256) {
            int r = f >> 5, c4 = f & 31;
            float4 v = x4[(size_t)(row0 + r) * 32 + c4];
            float4 sc = sc4[c4], sh = sh4[c4];
            float e0 = fmaf(v.x, sc.x, sh.x);
            float e1 = fmaf(v.y, sc.y, sh.y);
            float e2 = fmaf(v.z, sc.z, sh.z);
            float e3 = fmaf(v.w, sc.w, sh.w);
            int m = r >> 4, rr = r & 15;
            int g = rr & 7, rbit = rr >> 3;
            int kst = c4 >> 2;
            int kc  = 4 * (c4 & 3);
            int t   = (kc & 7) >> 1;
            int ri  = rbit + (kc >= 8 ? 2 : 0);
            unsigned* base = sy16 + (m * 8 + kst) * 128;
            base[((g * 4 + t)     ^ kst) * 4 + ri] = pkh2(e0, e1);
            base[((g * 4 + t + 1) ^ kst) * 4 + ri] = pkh2(e2, e3);
        }
    }
    __syncthreads();

    // ---- Phase 2: QKV GEMM, SINGLE pass, double-buffered B loads.
    //      Warp w: qk n-tiles {4w..4w+3} (fp16 acc) + v {32+2w,+1} (fp32 acc)
    {
        unsigned qkacc[MT][4][2];
        float    vacc [MT][2][4];
        #pragma unroll
        for (int m = 0; m < MT; ++m) {
            #pragma unroll
            for (int n = 0; n < 4; ++n) { qkacc[m][n][0] = 0u; qkacc[m][n][1] = 0u; }
            #pragma unroll
            for (int n = 0; n < 2; ++n)
                #pragma unroll
                for (int e = 0; e < 4; ++e) vacc[m][n][e] = 0.f;
        }

        #pragma unroll
        for (int kst = 0; kst < 8; ++kst) {
            const int cur = kst & 1, nxt = cur ^ 1;
            if (kst < 7) {
                #pragma unroll
                for (int n = 0; n < 4; ++n)
                    bqk[nxt][n] = __ldg(gqk + (n * 8 + kst + 1) * 32);
                #pragma unroll
                for (int n = 0; n < 2; ++n)
                    bv[nxt][n]  = __ldg(gv  + (n * 8 + kst + 1) * 32);
            }
            const int lx = lane ^ kst;
            #pragma unroll
            for (int m = 0; m < MT; ++m) {
                uint4 a = *(const uint4*)&sy16[(m * 8 + kst) * 128 + lx * 4];
                #pragma unroll
                for (int n = 0; n < 4; ++n)
                    mma_f16acc(qkacc[m][n][0], qkacc[m][n][1],
                               a.x, a.y, a.z, a.w, bqk[cur][n].x, bqk[cur][n].y);
                #pragma unroll
                for (int n = 0; n < 2; ++n)
                    mma_f16(vacc[m][n][0], vacc[m][n][1], vacc[m][n][2], vacc[m][n][3],
                            a.x, a.y, a.z, a.w, bv[cur][n].x, bv[cur][n].y);
            }
        }

        // scatter: q/k half2, v float2
        #pragma unroll
        for (int m = 0; m < MT; ++m) {
            int R0 = m * 16 + gid;
            int li0 = R0 / 10, i0 = R0 - li0 * 10;
            int R1 = R0 + 8;
            int li1 = R1 / 10, i1 = R1 - li1 * 10;
            #pragma unroll
            for (int n = 0; n < 4; ++n) {
                int Cn = (4 * wrp + n) * 8 + 2 * tig;
                int sel = Cn >> 7;
                int cc  = Cn & 127;
                int h   = cc >> 4;
                int dh  = cc & 15;
                unsigned short* dst = sel ? kh : qh;
                *(unsigned*)(dst + (li0 * 8 + h) * QH_BLK + i0 * 16 + dh) = qkacc[m][n][0];
                *(unsigned*)(dst + (li1 * 8 + h) * QH_BLK + i1 * 16 + dh) = qkacc[m][n][1];
            }
            #pragma unroll
            for (int n = 0; n < 2; ++n) {
                int cc = (2 * wrp + n) * 8 + 2 * tig;
                int h  = cc >> 4;
                int dh = cc & 15;
                *(float2*)&vv[(li0 * 8 + h) * V_BLK + i0 * 16 + dh] =
                    make_float2(vacc[m][n][0], vacc[m][n][1]);
                *(float2*)&vv[(li1 * 8 + h) * V_BLK + i1 * 16 + dh] =
                    make_float2(vacc[m][n][2], vacc[m][n][3]);
            }
        }
    }
    __syncthreads();

    // ---- Phase 3: masked attention, 4 threads/(item,head), rows sub+{0,4,8}
    //      fp16 dots, ex2 (log2e folded into mask), packed-fp32x2 AV accum.
    {
        const int pair = tid >> 2;          // 0..63 == li*8+h
        const int sub  = tid & 3;
        const int li = pair >> 3;
        const int h  = pair & 7;
        const unsigned short* qb = qh + pair * QH_BLK;
        const unsigned short* kb = kh + pair * QH_BLK;
        const float* vb = vv + pair * V_BLK;
        const int i0 = sub, i1 = sub + 4;
        const bool has3 = (sub < 2);
        const int i2 = has3 ? sub + 8 : sub;

        uint4 q0a = *(const uint4*)(qb + i0 * 16), q0b = *(const uint4*)(qb + i0 * 16 + 8);
        uint4 q1a = *(const uint4*)(qb + i1 * 16), q1b = *(const uint4*)(qb + i1 * 16 + 8);
        uint4 q2a = *(const uint4*)(qb + i2 * 16), q2b = *(const uint4*)(qb + i2 * 16 + 8);

        float d0[10], d1[10], d2[10];
        float s0 = 0.f, s1 = 0.f, s2 = 0.f;
        #pragma unroll
        for (int j = 0; j < 10; ++j) {
            uint4 ka = *(const uint4*)(kb + j * 16);
            uint4 kq = *(const uint4*)(kb + j * 16 + 8);
            // 0.25 logit scale folded into Wq; log2e folded into s_mask
            float p0 = hdot16(q0a, q0b, ka, kq) * s_mask[i0 * 10 + j];
            float p1 = hdot16(q1a, q1b, ka, kq) * s_mask[i1 * 10 + j];
            float p2 = hdot16(q2a, q2b, ka, kq) * s_mask[i2 * 10 + j];
            d0[j] = ex2f(p0); s0 += d0[j];
            d1[j] = ex2f(p1); s1 += d1[j];
            d2[j] = ex2f(p2); s2 += d2[j];
        }

        unsigned long long o0p[8], o1p[8], o2p[8];
        #pragma unroll
        for (int t = 0; t < 8; ++t) { o0p[t] = 0ull; o1p[t] = 0ull; o2p[t] = 0ull; }
        #pragma unroll
        for (int j = 0; j < 10; ++j) {
            unsigned long long pa0, pa1, pa2;
            BCAST2(pa0, d0[j]);
            BCAST2(pa1, d1[j]);
            BCAST2(pa2, d2[j]);
            const ulonglong2* vp = (const ulonglong2*)(vb + j * 16);
            ulonglong2 w0 = vp[0], w1 = vp[1], w2 = vp[2], w3 = vp[3];
            unsigned long long vr[8] = {w0.x, w0.y, w1.x, w1.y, w2.x, w2.y, w3.x, w3.y};
            #pragma unroll
            for (int t = 0; t < 8; ++t) {
                FMA2(o0p[t], pa0, vr[t]);
                FMA2(o1p[t], pa1, vr[t]);
                FMA2(o2p[t], pa2, vr[t]);
            }
        }
        // normalize by 1/sum (packed, rcp.approx)
        {
            unsigned long long pi0, pi1, pi2;
            BCAST2(pi0, rcpf(s0));
            BCAST2(pi1, rcpf(s1));
            BCAST2(pi2, rcpf(s2));
            #pragma unroll
            for (int t = 0; t < 8; ++t) {
                MUL2(o0p[t], pi0);
                MUL2(o1p[t], pi1);
                MUL2(o2p[t], pi2);
            }
        }

        // scatter rows as fp16 fragments: channels h*16+c -> tile (m, kst=h)
        #pragma unroll
        for (int rep = 0; rep < 3; ++rep) {
            if (rep == 2 && !has3) break;
            const unsigned long long* o = rep == 0 ? o0p : (rep == 1 ? o1p : o2p);
            int i = rep == 0 ? i0 : (rep == 1 ? i1 : i2);
            int R = li * 10 + i;
            int m = R >> 4, rr = R & 15;
            int g = rr & 7, rbit = rr >> 3;
            unsigned* base = sy16 + (m * 8 + h) * 128;
            #pragma unroll
            for (int t = 0; t < 4; ++t) {
                int ln = ((g * 4 + t) ^ h) * 4;
                float lo, hi, lo2, hi2;
                UNPK2(lo, hi, o[t]);
                UNPK2(lo2, hi2, o[t + 4]);
                base[ln + rbit]     = pkh2(lo, hi);
                base[ln + rbit + 2] = pkh2(lo2, hi2);
            }
        }
    }

    // P4 kst=0 weight preload: issued before the barrier so the L2 latency
    // hides behind the barrier wait.
    const uint2* gwp4 = g_wout16 + (2 * wrp) * 8 * 32 + lane;
    uint2 b4[2][2];
    #pragma unroll
    for (int n = 0; n < 2; ++n) b4[0][n] = __ldg(gwp4 + n * 8 * 32);
    __syncthreads();

    // ---- Phase 4: out projection, all 8 warps, 2 n-tiles each (fp32 acc),
    //      double-buffered B loads. -----------------------------------------
    {
        float acc[MT][2][4];
        #pragma unroll
        for (int m = 0; m < MT; ++m)
            #pragma unroll
            for (int n = 0; n < 2; ++n)
                #pragma unroll
                for (int e = 0; e < 4; ++e) acc[m][n][e] = 0.f;

        #pragma unroll
        for (int kst = 0; kst < 8; ++kst) {
            const int cur = kst & 1, nxt = cur ^ 1;
            if (kst < 7) {
                #pragma unroll
                for (int n = 0; n < 2; ++n)
                    b4[nxt][n] = __ldg(gwp4 + (n * 8 + kst + 1) * 32);
            }
            const int lx = lane ^ kst;
            #pragma unroll
            for (int m = 0; m < MT; ++m) {
                uint4 a = *(const uint4*)&sy16[(m * 8 + kst) * 128 + lx * 4];
                #pragma unroll
                for (int n = 0; n < 2; ++n)
                    mma_f16(acc[m][n][0], acc[m][n][1], acc[m][n][2], acc[m][n][3],
                            a.x, a.y, a.z, a.w, b4[cur][n].x, b4[cur][n].y);
            }
        }

        #pragma unroll
        for (int m = 0; m < MT; ++m)
            #pragma unroll
            for (int n = 0; n < 2; ++n) {
                int col = (2 * wrp + n) * 8 + 2 * tig;
                float b0 = s_bout[col], b1 = s_bout[col + 1];
                int R0 = m * 16 + gid;
                *(float2*)&out[(size_t)(row0 + R0) * 128 + col] =
                    make_float2(acc[m][n][0] + b0, acc[m][n][1] + b1);
                *(float2*)&out[(size_t)(row0 + R0 + 8) * 128 + col] =
                    make_float2(acc[m][n][2] + b0, acc[m][n][3] + b1);
            }
    }
}

// ---------------------------------------------------------------------------
extern "C" void kernel_launch(void* const* d_in, const int* in_sizes, int n_in,
                              void* d_out, int out_size) {
    const float* x     = (const float*)d_in[0];
    const float* gamma = (const float*)d_in[1];
    const float* beta  = (const float*)d_in[2];
    const float* w_qkv = (const float*)d_in[3];
    const float* w_out = (const float*)d_in[4];
    const float* b_out = (const float*)d_in[5];
    const float* mask  = (const float*)d_in[6];
    float* out = (float*)d_out;

    cudaFuncSetAttribute(main_kernel,
                         cudaFuncAttributeMaxDynamicSharedMemorySize, SMEM_BYTES);

    stats_kernel<<<NBLK_STATS, 256>>>((const float4*)x);
    prep_kernel<<<13, 1024>>>(gamma, beta, w_qkv, w_out);
    main_kernel<<<BTOT / NB, 256, SMEM_BYTES>>>(x, b_out, mask, out);
}

// round 12
// speedup vs baseline: 1.0758x; 1.0758x over previous
#include <cuda_runtime.h>
#include <cuda_fp16.h>

// ---------------------------------------------------------------------------
// Problem constants
#define R_TOTAL   327680          // N*T*VN rows
#define BTOT      32768           // N*T graph items
#define NB        8               // items per block
#define ROWS      (NB*10)         // 80 rows per block = 5 m-tiles, NO padding
#define MT        5               // m-tiles
#define NBLK_STATS 2048
#define NBLK_PERM  48
#define BN_EPS    1e-5f

// Scratch (allocation-free)
__device__ float g_psum[NBLK_STATS * 128];
__device__ float g_psq [NBLK_STATS * 128];
__device__ float g_scale[128];
__device__ float g_shift[128];
__device__ unsigned g_done_count = 0;     // last-block barrier; self-resets
// Pre-permuted fp16 weights in m16n8k16 B-fragment order:
// [nt][kst(8)][lane(32)] -> uint2 {b0 = W[k0,k0+1][n], b1 = W[k0+8,k0+9][n]}
// q-part (nt 0..15) pre-scaled by 0.25 (the attention logit scale; exact pow2)
__device__ uint2 g_wqkv16[48 * 8 * 32];
__device__ uint2 g_wout16[16 * 8 * 32];

// ---------------------------------------------------------------------------
__device__ __forceinline__ unsigned pkh2(float a, float b) {
    __half2 h = __floats2half2_rn(a, b);
    return *(unsigned*)&h;
}
__device__ __forceinline__ __half2 u2h2(unsigned u) { return *(__half2*)&u; }

// fp32-accumulator fp16 mma
__device__ __forceinline__ void mma_f16(float& c0, float& c1, float& c2, float& c3,
                                        unsigned a0, unsigned a1, unsigned a2, unsigned a3,
                                        unsigned b0, unsigned b1) {
    asm volatile("mma.sync.aligned.m16n8k16.row.col.f32.f16.f16.f32 "
                 "{%0,%1,%2,%3}, {%4,%5,%6,%7}, {%8,%9}, {%0,%1,%2,%3};\n"
                 : "+f"(c0), "+f"(c1), "+f"(c2), "+f"(c3)
                 : "r"(a0), "r"(a1), "r"(a2), "r"(a3), "r"(b0), "r"(b1));
}

// fp16-accumulator fp16 mma (C/D packed half2 x2)
__device__ __forceinline__ void mma_f16acc(unsigned& c0, unsigned& c1,
                                           unsigned a0, unsigned a1, unsigned a2, unsigned a3,
                                           unsigned b0, unsigned b1) {
    asm volatile("mma.sync.aligned.m16n8k16.row.col.f16.f16.f16.f16 "
                 "{%0,%1}, {%2,%3,%4,%5}, {%6,%7}, {%0,%1};\n"
                 : "+r"(c0), "+r"(c1)
                 : "r"(a0), "r"(a1), "r"(a2), "r"(a3), "r"(b0), "r"(b1));
}

// packed fp32x2 ops (Blackwell FFMA2 — PTX-only)
#define FMA2(o, a, v) asm("fma.rn.f32x2 %0, %1, %2, %0;" : "+l"(o) : "l"(a), "l"(v))
#define MUL2(o, s)    asm("mul.rn.f32x2 %0, %0, %1;"     : "+l"(o) : "l"(s))
#define BCAST2(o, f)  asm("mov.b64 %0, {%1, %1};"        : "=l"(o) : "f"(f))
#define UNPK2(lo, hi, o) asm("mov.b64 {%0, %1}, %2;" : "=f"(lo), "=f"(hi) : "l"(o))

__device__ __forceinline__ float ex2f(float x) {
    float r;
    asm("ex2.approx.f32 %0, %1;" : "=f"(r) : "f"(x));
    return r;
}
__device__ __forceinline__ float rcpf(float x) {
    float r;
    asm("rcp.approx.f32 %0, %1;" : "=f"(r) : "f"(x));
    return r;
}

// half2 dot of 16 fp16 values (2x uint4), fp32 finish
__device__ __forceinline__ float hdot16(uint4 qa, uint4 qb, uint4 ka, uint4 kb) {
    __half2 s = __hmul2(u2h2(qa.x), u2h2(ka.x));
    s = __hfma2(u2h2(qa.y), u2h2(ka.y), s);
    s = __hfma2(u2h2(qa.z), u2h2(ka.z), s);
    s = __hfma2(u2h2(qa.w), u2h2(ka.w), s);
    s = __hfma2(u2h2(qb.x), u2h2(kb.x), s);
    s = __hfma2(u2h2(qb.y), u2h2(kb.y), s);
    s = __hfma2(u2h2(qb.z), u2h2(kb.z), s);
    s = __hfma2(u2h2(qb.w), u2h2(kb.w), s);
    float2 f = __half22float2(s);
    return f.x + f.y;
}

// ---------------------------------------------------------------------------
// Kernel 1 (fused front): blocks 0..2047 stats (+ last block finalizes),
//                         blocks 2048..2095 weight permute
// ---------------------------------------------------------------------------
__global__ void __launch_bounds__(256) front_kernel(const float4* __restrict__ x4,
                                                    const float* __restrict__ gamma,
                                                    const float* __restrict__ beta,
                                                    const float* __restrict__ wqkv,
                                                    const float* __restrict__ wout) {
    const int tid = threadIdx.x;

    if (blockIdx.x >= NBLK_STATS) {
        // ---- weight permute into fp16 m16n8k16 B-fragment order ----------
        int idx = (blockIdx.x - NBLK_STATS) * 256 + tid;     // 0..12287
        {
            int lane = idx & 31;
            int kst  = (idx >> 5) & 7;
            int nt   = idx >> 8;                             // 0..47
            int tig = lane & 3, gid = lane >> 2;
            int k0 = kst * 16 + 2 * tig;
            int n  = nt * 8 + gid;
            float s = (nt < 16) ? 0.25f : 1.0f;              // fold logit scale
            uint2 v;
            v.x = pkh2(s * wqkv[k0 * 384 + n],       s * wqkv[(k0 + 1) * 384 + n]);
            v.y = pkh2(s * wqkv[(k0 + 8) * 384 + n], s * wqkv[(k0 + 9) * 384 + n]);
            g_wqkv16[idx] = v;
        }
        if (idx < 16 * 8 * 32) {
            int lane = idx & 31;
            int kst  = (idx >> 5) & 7;
            int nt   = idx >> 8;                             // 0..15
            int tig = lane & 3, gid = lane >> 2;
            int k0 = kst * 16 + 2 * tig;
            int n  = nt * 8 + gid;
            uint2 v;
            v.x = pkh2(wout[k0 * 128 + n],       wout[(k0 + 1) * 128 + n]);
            v.y = pkh2(wout[(k0 + 8) * 128 + n], wout[(k0 + 9) * 128 + n]);
            g_wout16[idx] = v;
        }
        return;
    }

    // ---- stats: per-channel sum / sumsq partials --------------------------
    __shared__ float s_sum[256][4];
    __shared__ float s_sq [256][4];
    const int lane = tid & 31;
    const int slot = tid >> 5;

    float4 sum = make_float4(0.f, 0.f, 0.f, 0.f);
    float4 sq  = make_float4(0.f, 0.f, 0.f, 0.f);

    int row = blockIdx.x * 8 + slot;
    const int stride = NBLK_STATS * 8;
    #pragma unroll 8
    for (int it = 0; it < R_TOTAL / stride; ++it) {
        float4 v = x4[(size_t)row * 32 + lane];
        sum.x += v.x; sum.y += v.y; sum.z += v.z; sum.w += v.w;
        sq.x += v.x * v.x; sq.y += v.y * v.y; sq.z += v.z * v.z; sq.w += v.w * v.w;
        row += stride;
    }
    s_sum[tid][0] = sum.x; s_sum[tid][1] = sum.y; s_sum[tid][2] = sum.z; s_sum[tid][3] = sum.w;
    s_sq [tid][0] = sq.x;  s_sq [tid][1] = sq.y;  s_sq [tid][2] = sq.z;  s_sq [tid][3] = sq.w;
    __syncthreads();
    for (int off = 128; off >= 32; off >>= 1) {
        if (tid < off) {
            #pragma unroll
            for (int j = 0; j < 4; ++j) {
                s_sum[tid][j] += s_sum[tid + off][j];
                s_sq [tid][j] += s_sq [tid + off][j];
            }
        }
        __syncthreads();
    }
    if (tid < 32) {
        #pragma unroll
        for (int j = 0; j < 4; ++j) {
            g_psum[blockIdx.x * 128 + tid * 4 + j] = s_sum[tid][j];
            g_psq [blockIdx.x * 128 + tid * 4 + j] = s_sq [tid][j];
        }
    }

    // ---- last-block finalize (threadfence reduction pattern) --------------
    __shared__ bool is_last;
    __threadfence();
    if (tid == 0) {
        unsigned old = atomicAdd(&g_done_count, 1u);
        is_last = (old == NBLK_STATS - 1);
    }
    __syncthreads();
    if (!is_last) return;

    {
        // 256 threads: c4 = tid&31 (4 channels via float4), s = tid>>5 (8 slices)
        const int c4 = tid & 31;
        const int s  = tid >> 5;
        const float4* p4 = (const float4*)g_psum;
        const float4* q4 = (const float4*)g_psq;
        float4 S = make_float4(0.f, 0.f, 0.f, 0.f);
        float4 Q = make_float4(0.f, 0.f, 0.f, 0.f);
        #pragma unroll 8
        for (int b = s; b < NBLK_STATS; b += 8) {
            float4 a = p4[b * 32 + c4];
            float4 c = q4[b * 32 + c4];
            S.x += a.x; S.y += a.y; S.z += a.z; S.w += a.w;
            Q.x += c.x; Q.y += c.y; Q.z += c.z; Q.w += c.w;
        }
        s_sum[s * 32 + c4][0] = S.x; s_sum[s * 32 + c4][1] = S.y;
        s_sum[s * 32 + c4][2] = S.z; s_sum[s * 32 + c4][3] = S.w;
        s_sq [s * 32 + c4][0] = Q.x; s_sq [s * 32 + c4][1] = Q.y;
        s_sq [s * 32 + c4][2] = Q.z; s_sq [s * 32 + c4][3] = Q.w;
        __syncthreads();
        if (tid < 32) {
            float S4[4] = {0.f, 0.f, 0.f, 0.f};
            float Q4[4] = {0.f, 0.f, 0.f, 0.f};
            #pragma unroll
            for (int j = 0; j < 8; ++j)
                #pragma unroll
                for (int e = 0; e < 4; ++e) {
                    S4[e] += s_sum[j * 32 + tid][e];
                    Q4[e] += s_sq [j * 32 + tid][e];
                }
            const float inv_n = 1.0f / (float)R_TOTAL;
            #pragma unroll
            for (int e = 0; e < 4; ++e) {
                int c = tid * 4 + e;
                float mean = S4[e] * inv_n;
                float var  = Q4[e] * inv_n - mean * mean;
                float sc   = gamma[c] * rsqrtf(var + BN_EPS);
                g_scale[c] = sc;
                g_shift[c] = beta[c] - mean * sc;
            }
        }
        if (tid == 0) g_done_count = 0;   // reset for next graph replay
    }
}

// ---------------------------------------------------------------------------
// Kernel 2: fused BN-normalize -> QKV (fp16 mma) -> attention -> out-proj
// 256 threads, 2 blocks/SM — R10-verified structure, registers saturated:
// DO NOT add live state to this kernel.
// smem: sy16 20KB | qh/kh fp16 21KB each | vv fp32 41KB | small 2KB = ~107KB
// ---------------------------------------------------------------------------
#define QH_BLK   168                        // per-pair q/k stride in halves
#define V_BLK    164                        // per-pair v stride in floats
#define SY_U32   (MT * 8 * 128)             // 5120
#define SMEM_FLOATS (SY_U32 + 2 * (64 * QH_BLK / 2) + 64 * V_BLK + 512)
#define SMEM_BYTES  (SMEM_FLOATS * 4)

__global__ void __launch_bounds__(256, 2)
main_kernel(const float* __restrict__ x,
            const float* __restrict__ b_out,
            const float* __restrict__ mask,
            float* __restrict__ out) {
    extern __shared__ float sm[];
    unsigned* sy16 = (unsigned*)sm;               // [mt][kst][lane^kst][4 regs]
    unsigned short* qh = (unsigned short*)(sm + SY_U32);
    unsigned short* kh = qh + 64 * QH_BLK;
    float* vv      = sm + SY_U32 + (64 * QH_BLK); // after qh+kh (2*168*64 halves)
    float* s_scale = vv + 64 * V_BLK;
    float* s_shift = s_scale + 128;
    float* s_mask  = s_shift + 128;               // mask * log2(e)
    float* s_bout  = s_mask + 128;

    const int tid  = threadIdx.x;
    const int lane = tid & 31;
    const int wrp  = tid >> 5;
    const int tig  = lane & 3;
    const int gid  = lane >> 2;
    const int row0 = blockIdx.x * ROWS;

    if (tid < 128) {
        s_scale[tid] = g_scale[tid];
        s_shift[tid] = g_shift[tid];
        s_bout [tid] = b_out[tid];
    }
    if (tid < 100) s_mask[tid] = mask[tid] * 1.44269504f;  // fold log2e for ex2
    __syncthreads();

    // ---- Phase 1: load + BN-normalize x into fp16 A-fragment sy (no pad) ---
    {
        const float4* x4  = (const float4*)x;
        const float4* sc4 = (const float4*)s_scale;
        const float4* sh4 = (const float4*)s_shift;
        #pragma unroll
        for (int f = tid; f < MT * 16 * 32; f += 256) {
            int r = f >> 5, c4 = f & 31;
            float4 v = x4[(size_t)(row0 + r) * 32 + c4];
            float4 sc = sc4[c4], sh = sh4[c4];
            float e0 = fmaf(v.x, sc.x, sh.x);
            float e1 = fmaf(v.y, sc.y, sh.y);
            float e2 = fmaf(v.z, sc.z, sh.z);
            float e3 = fmaf(v.w, sc.w, sh.w);
            int m = r >> 4, rr = r & 15;
            int g = rr & 7, rbit = rr >> 3;
            int kst = c4 >> 2;
            int kc  = 4 * (c4 & 3);
            int t   = (kc & 7) >> 1;
            int ri  = rbit + (kc >= 8 ? 2 : 0);
            unsigned* base = sy16 + (m * 8 + kst) * 128;
            base[((g * 4 + t)     ^ kst) * 4 + ri] = pkh2(e0, e1);
            base[((g * 4 + t + 1) ^ kst) * 4 + ri] = pkh2(e2, e3);
        }
    }
    __syncthreads();

    // ---- Phase 2: QKV GEMM, SINGLE pass. Warp w: qk n-tiles {4w..4w+3}
    //      (fp16 accumulators) + v n-tiles {32+2w, 32+2w+1} (fp32 acc)
    {
        unsigned qkacc[MT][4][2];
        float    vacc [MT][2][4];
        #pragma unroll
        for (int m = 0; m < MT; ++m) {
            #pragma unroll
            for (int n = 0; n < 4; ++n) { qkacc[m][n][0] = 0u; qkacc[m][n][1] = 0u; }
            #pragma unroll
            for (int n = 0; n < 2; ++n)
                #pragma unroll
                for (int e = 0; e < 4; ++e) vacc[m][n][e] = 0.f;
        }

        const uint2* gqk = g_wqkv16 + (4 * wrp) * 8 * 32 + lane;
        const uint2* gv  = g_wqkv16 + (32 + 2 * wrp) * 8 * 32 + lane;

        #pragma unroll 2
        for (int kst = 0; kst < 8; ++kst) {
            uint2 bqk[4], bv[2];
            #pragma unroll
            for (int n = 0; n < 4; ++n) bqk[n] = __ldg(gqk + (n * 8 + kst) * 32);
            #pragma unroll
            for (int n = 0; n < 2; ++n) bv[n]  = __ldg(gv  + (n * 8 + kst) * 32);
            const int lx = lane ^ kst;
            #pragma unroll
            for (int m = 0; m < MT; ++m) {
                uint4 a = *(const uint4*)&sy16[(m * 8 + kst) * 128 + lx * 4];
                #pragma unroll
                for (int n = 0; n < 4; ++n)
                    mma_f16acc(qkacc[m][n][0], qkacc[m][n][1],
                               a.x, a.y, a.z, a.w, bqk[n].x, bqk[n].y);
                #pragma unroll
                for (int n = 0; n < 2; ++n)
                    mma_f16(vacc[m][n][0], vacc[m][n][1], vacc[m][n][2], vacc[m][n][3],
                            a.x, a.y, a.z, a.w, bv[n].x, bv[n].y);
            }
        }

        // scatter: q/k half2, v float2
        #pragma unroll
        for (int m = 0; m < MT; ++m) {
            int R0 = m * 16 + gid;
            int li0 = R0 / 10, i0 = R0 - li0 * 10;
            int R1 = R0 + 8;
            int li1 = R1 / 10, i1 = R1 - li1 * 10;
            #pragma unroll
            for (int n = 0; n < 4; ++n) {
                int Cn = (4 * wrp + n) * 8 + 2 * tig;
                int sel = Cn >> 7;
                int cc  = Cn & 127;
                int h   = cc >> 4;
                int dh  = cc & 15;
                unsigned short* dst = sel ? kh : qh;
                *(unsigned*)(dst + (li0 * 8 + h) * QH_BLK + i0 * 16 + dh) = qkacc[m][n][0];
                *(unsigned*)(dst + (li1 * 8 + h) * QH_BLK + i1 * 16 + dh) = qkacc[m][n][1];
            }
            #pragma unroll
            for (int n = 0; n < 2; ++n) {
                int cc = (2 * wrp + n) * 8 + 2 * tig;
                int h  = cc >> 4;
                int dh = cc & 15;
                *(float2*)&vv[(li0 * 8 + h) * V_BLK + i0 * 16 + dh] =
                    make_float2(vacc[m][n][0], vacc[m][n][1]);
                *(float2*)&vv[(li1 * 8 + h) * V_BLK + i1 * 16 + dh] =
                    make_float2(vacc[m][n][2], vacc[m][n][3]);
            }
        }
    }
    __syncthreads();

    // ---- Phase 3: masked attention, 4 threads/(item,head), rows sub+{0,4,8}
    //      fp16 dots, ex2 (log2e folded into mask), packed-fp32x2 AV accum.
    {
        const int pair = tid >> 2;          // 0..63 == li*8+h
        const int sub  = tid & 3;
        const int li = pair >> 3;
        const int h  = pair & 7;
        const unsigned short* qb = qh + pair * QH_BLK;
        const unsigned short* kb = kh + pair * QH_BLK;
        const float* vb = vv + pair * V_BLK;
        const int i0 = sub, i1 = sub + 4;
        const bool has3 = (sub < 2);
        const int i2 = has3 ? sub + 8 : sub;

        uint4 q0a = *(const uint4*)(qb + i0 * 16), q0b = *(const uint4*)(qb + i0 * 16 + 8);
        uint4 q1a = *(const uint4*)(qb + i1 * 16), q1b = *(const uint4*)(qb + i1 * 16 + 8);
        uint4 q2a = *(const uint4*)(qb + i2 * 16), q2b = *(const uint4*)(qb + i2 * 16 + 8);

        float d0[10], d1[10], d2[10];
        float s0 = 0.f, s1 = 0.f, s2 = 0.f;
        #pragma unroll
        for (int j = 0; j < 10; ++j) {
            uint4 ka = *(const uint4*)(kb + j * 16);
            uint4 kq = *(const uint4*)(kb + j * 16 + 8);
            // 0.25 logit scale folded into Wq; log2e folded into s_mask
            float p0 = hdot16(q0a, q0b, ka, kq) * s_mask[i0 * 10 + j];
            float p1 = hdot16(q1a, q1b, ka, kq) * s_mask[i1 * 10 + j];
            float p2 = hdot16(q2a, q2b, ka, kq) * s_mask[i2 * 10 + j];
            d0[j] = ex2f(p0); s0 += d0[j];
            d1[j] = ex2f(p1); s1 += d1[j];
            d2[j] = ex2f(p2); s2 += d2[j];
        }

        unsigned long long o0p[8], o1p[8], o2p[8];
        #pragma unroll
        for (int t = 0; t < 8; ++t) { o0p[t] = 0ull; o1p[t] = 0ull; o2p[t] = 0ull; }
        #pragma unroll
        for (int j = 0; j < 10; ++j) {
            unsigned long long pa0, pa1, pa2;
            BCAST2(pa0, d0[j]);
            BCAST2(pa1, d1[j]);
            BCAST2(pa2, d2[j]);
            const ulonglong2* vp = (const ulonglong2*)(vb + j * 16);
            ulonglong2 w0 = vp[0], w1 = vp[1], w2 = vp[2], w3 = vp[3];
            unsigned long long vr[8] = {w0.x, w0.y, w1.x, w1.y, w2.x, w2.y, w3.x, w3.y};
            #pragma unroll
            for (int t = 0; t < 8; ++t) {
                FMA2(o0p[t], pa0, vr[t]);
                FMA2(o1p[t], pa1, vr[t]);
                FMA2(o2p[t], pa2, vr[t]);
            }
        }
        // normalize by 1/sum (packed, rcp.approx)
        {
            unsigned long long pi0, pi1, pi2;
            BCAST2(pi0, rcpf(s0));
            BCAST2(pi1, rcpf(s1));
            BCAST2(pi2, rcpf(s2));
            #pragma unroll
            for (int t = 0; t < 8; ++t) {
                MUL2(o0p[t], pi0);
                MUL2(o1p[t], pi1);
                MUL2(o2p[t], pi2);
            }
        }

        // scatter rows as fp16 fragments: channels h*16+c -> tile (m, kst=h)
        #pragma unroll
        for (int rep = 0; rep < 3; ++rep) {
            if (rep == 2 && !has3) break;
            const unsigned long long* o = rep == 0 ? o0p : (rep == 1 ? o1p : o2p);
            int i = rep == 0 ? i0 : (rep == 1 ? i1 : i2);
            int R = li * 10 + i;
            int m = R >> 4, rr = R & 15;
            int g = rr & 7, rbit = rr >> 3;
            unsigned* base = sy16 + (m * 8 + h) * 128;
            #pragma unroll
            for (int t = 0; t < 4; ++t) {
                int ln = ((g * 4 + t) ^ h) * 4;
                float lo, hi, lo2, hi2;
                UNPK2(lo, hi, o[t]);
                UNPK2(lo2, hi2, o[t + 4]);
                base[ln + rbit]     = pkh2(lo, hi);
                base[ln + rbit + 2] = pkh2(lo2, hi2);
            }
        }
    }
    __syncthreads();

    // ---- Phase 4: out projection, all 8 warps, 2 n-tiles each (fp32 acc) ---
    {
        float acc[MT][2][4];
        #pragma unroll
        for (int m = 0; m < MT; ++m)
            #pragma unroll
            for (int n = 0; n < 2; ++n)
                #pragma unroll
                for (int e = 0; e < 4; ++e) acc[m][n][e] = 0.f;

        const int nt0 = 2 * wrp;
        const uint2* gwp = g_wout16 + nt0 * 8 * 32 + lane;

        #pragma unroll 4
        for (int kst = 0; kst < 8; ++kst) {
            uint2 b[2];
            #pragma unroll
            for (int n = 0; n < 2; ++n)
                b[n] = __ldg(gwp + (n * 8 + kst) * 32);
            const int lx = lane ^ kst;
            #pragma unroll
            for (int m = 0; m < MT; ++m) {
                uint4 a = *(const uint4*)&sy16[(m * 8 + kst) * 128 + lx * 4];
                #pragma unroll
                for (int n = 0; n < 2; ++n)
                    mma_f16(acc[m][n][0], acc[m][n][1], acc[m][n][2], acc[m][n][3],
                            a.x, a.y, a.z, a.w, b[n].x, b[n].y);
            }
        }

        #pragma unroll
        for (int m = 0; m < MT; ++m)
            #pragma unroll
            for (int n = 0; n < 2; ++n) {
                int col = (nt0 + n) * 8 + 2 * tig;
                float b0 = s_bout[col], b1 = s_bout[col + 1];
                int R0 = m * 16 + gid;
                *(float2*)&out[(size_t)(row0 + R0) * 128 + col] =
                    make_float2(acc[m][n][0] + b0, acc[m][n][1] + b1);
                *(float2*)&out[(size_t)(row0 + R0 + 8) * 128 + col] =
                    make_float2(acc[m][n][2] + b0, acc[m][n][3] + b1);
            }
    }
}

// ---------------------------------------------------------------------------
extern "C" void kernel_launch(void* const* d_in, const int* in_sizes, int n_in,
                              void* d_out, int out_size) {
    const float* x     = (const float*)d_in[0];
    const float* gamma = (const float*)d_in[1];
    const float* beta  = (const float*)d_in[2];
    const float* w_qkv = (const float*)d_in[3];
    const float* w_out = (const float*)d_in[4];
    const float* b_out = (const float*)d_in[5];
    const float* mask  = (const float*)d_in[6];
    float* out = (float*)d_out;

    cudaFuncSetAttribute(main_kernel,
                         cudaFuncAttributeMaxDynamicSharedMemorySize, SMEM_BYTES);

    front_kernel<<<NBLK_STATS + NBLK_PERM, 256>>>((const float4*)x, gamma, beta,
                                                  w_qkv, w_out);
    main_kernel<<<BTOT / NB, 256, SMEM_BYTES>>>(x, b_out, mask, out);
}

// round 15
// speedup vs baseline: 1.4823x; 1.3778x over previous
#include <cuda_runtime.h>
#include <cuda_fp16.h>

// ---------------------------------------------------------------------------
// Problem constants
#define R_TOTAL   327680          // N*T*VN rows
#define BTOT      32768           // N*T graph items
#define NB        8               // items per block
#define ROWS      (NB*10)         // 80 rows per block = 5 m-tiles, NO padding
#define MT        5               // m-tiles
#define NBLK_STATS 1024
#define NBLK_PERM  48
#define BN_EPS    1e-5f

// Scratch (allocation-free)
__device__ float g_psum[NBLK_STATS * 128];
__device__ float g_psq [NBLK_STATS * 128];
__device__ float g_scale[128];
__device__ float g_shift[128];
// Pre-permuted fp16 weights in m16n8k16 B-fragment order:
// [nt][kst(8)][lane(32)] -> uint2 {b0 = W[k0,k0+1][n], b1 = W[k0+8,k0+9][n]}
// q-part (nt 0..15) pre-scaled by 0.25 (the attention logit scale; exact pow2)
__device__ uint2 g_wqkv16[48 * 8 * 32];
__device__ uint2 g_wout16[16 * 8 * 32];

// ---------------------------------------------------------------------------
__device__ __forceinline__ unsigned pkh2(float a, float b) {
    __half2 h = __floats2half2_rn(a, b);
    return *(unsigned*)&h;
}
__device__ __forceinline__ __half2 u2h2(unsigned u) { return *(__half2*)&u; }

// fp32-accumulator fp16 mma
__device__ __forceinline__ void mma_f16(float& c0, float& c1, float& c2, float& c3,
                                        unsigned a0, unsigned a1, unsigned a2, unsigned a3,
                                        unsigned b0, unsigned b1) {
    asm volatile("mma.sync.aligned.m16n8k16.row.col.f32.f16.f16.f32 "
                 "{%0,%1,%2,%3}, {%4,%5,%6,%7}, {%8,%9}, {%0,%1,%2,%3};\n"
                 : "+f"(c0), "+f"(c1), "+f"(c2), "+f"(c3)
                 : "r"(a0), "r"(a1), "r"(a2), "r"(a3), "r"(b0), "r"(b1));
}

// fp16-accumulator fp16 mma (C/D packed half2 x2)
__device__ __forceinline__ void mma_f16acc(unsigned& c0, unsigned& c1,
                                           unsigned a0, unsigned a1, unsigned a2, unsigned a3,
                                           unsigned b0, unsigned b1) {
    asm volatile("mma.sync.aligned.m16n8k16.row.col.f16.f16.f16.f16 "
                 "{%0,%1}, {%2,%3,%4,%5}, {%6,%7}, {%0,%1};\n"
                 : "+r"(c0), "+r"(c1)
                 : "r"(a0), "r"(a1), "r"(a2), "r"(a3), "r"(b0), "r"(b1));
}

// packed fp32x2 ops (Blackwell FFMA2 — PTX-only)
#define FMA2(o, a, v) asm("fma.rn.f32x2 %0, %1, %2, %0;" : "+l"(o) : "l"(a), "l"(v))
#define MUL2(o, s)    asm("mul.rn.f32x2 %0, %0, %1;"     : "+l"(o) : "l"(s))
#define BCAST2(o, f)  asm("mov.b64 %0, {%1, %1};"        : "=l"(o) : "f"(f))
#define UNPK2(lo, hi, o) asm("mov.b64 {%0, %1}, %2;" : "=f"(lo), "=f"(hi) : "l"(o))

__device__ __forceinline__ float ex2f(float x) {
    float r;
    asm("ex2.approx.f32 %0, %1;" : "=f"(r) : "f"(x));
    return r;
}
__device__ __forceinline__ float rcpf(float x) {
    float r;
    asm("rcp.approx.f32 %0, %1;" : "=f"(r) : "f"(x));
    return r;
}

// half2 dot of 16 fp16 values (2x uint4), fp32 finish
__device__ __forceinline__ float hdot16(uint4 qa, uint4 qb, uint4 ka, uint4 kb) {
    __half2 s = __hmul2(u2h2(qa.x), u2h2(ka.x));
    s = __hfma2(u2h2(qa.y), u2h2(ka.y), s);
    s = __hfma2(u2h2(qa.z), u2h2(ka.z), s);
    s = __hfma2(u2h2(qa.w), u2h2(ka.w), s);
    s = __hfma2(u2h2(qb.x), u2h2(kb.x), s);
    s = __hfma2(u2h2(qb.y), u2h2(kb.y), s);
    s = __hfma2(u2h2(qb.z), u2h2(kb.z), s);
    s = __hfma2(u2h2(qb.w), u2h2(kb.w), s);
    float2 f = __half22float2(s);
    return f.x + f.y;
}

// ---------------------------------------------------------------------------
// Kernel 1 (fused): blocks 0..1023 stats partials (2 rows/thread/iter),
//                   blocks 1024..1071 weight permute. NO serial tail.
// ---------------------------------------------------------------------------
__global__ void __launch_bounds__(256) front_kernel(const float4* __restrict__ x4,
                                                    const float* __restrict__ wqkv,
                                                    const float* __restrict__ wout) {
    const int tid = threadIdx.x;

    if (blockIdx.x >= NBLK_STATS) {
        // ---- weight permute into fp16 m16n8k16 B-fragment order ----------
        int idx = (blockIdx.x - NBLK_STATS) * 256 + tid;     // 0..12287
        {
            int lane = idx & 31;
            int kst  = (idx >> 5) & 7;
            int nt   = idx >> 8;                             // 0..47
            int tig = lane & 3, gid = lane >> 2;
            int k0 = kst * 16 + 2 * tig;
            int n  = nt * 8 + gid;
            float s = (nt < 16) ? 0.25f : 1.0f;              // fold logit scale
            uint2 v;
            v.x = pkh2(s * wqkv[k0 * 384 + n],       s * wqkv[(k0 + 1) * 384 + n]);
            v.y = pkh2(s * wqkv[(k0 + 8) * 384 + n], s * wqkv[(k0 + 9) * 384 + n]);
            g_wqkv16[idx] = v;
        }
        if (idx < 16 * 8 * 32) {
            int lane = idx & 31;
            int kst  = (idx >> 5) & 7;
            int nt   = idx >> 8;                             // 0..15
            int tig = lane & 3, gid = lane >> 2;
            int k0 = kst * 16 + 2 * tig;
            int n  = nt * 8 + gid;
            uint2 v;
            v.x = pkh2(wout[k0 * 128 + n],       wout[(k0 + 1) * 128 + n]);
            v.y = pkh2(wout[(k0 + 8) * 128 + n], wout[(k0 + 9) * 128 + n]);
            g_wout16[idx] = v;
        }
        return;
    }

    // ---- stats: per-channel sum/sumsq, 2 rows per thread per iter ---------
    __shared__ float s_sum[256][4];
    __shared__ float s_sq [256][4];
    const int lane = tid & 31;
    const int slot = tid >> 5;            // 0..7

    float4 sum = make_float4(0.f, 0.f, 0.f, 0.f);
    float4 sq  = make_float4(0.f, 0.f, 0.f, 0.f);

    int row = blockIdx.x * 16 + slot;     // rows row and row+8 (same channels)
    const int stride = NBLK_STATS * 16;   // 16384 rows per sweep, 20 sweeps
    #pragma unroll 4
    for (int it = 0; it < R_TOTAL / stride; ++it) {
        float4 v = x4[(size_t)row * 32 + lane];
        float4 w = x4[(size_t)(row + 8) * 32 + lane];
        sum.x += v.x + w.x; sum.y += v.y + w.y;
        sum.z += v.z + w.z; sum.w += v.w + w.w;
        sq.x += v.x * v.x + w.x * w.x; sq.y += v.y * v.y + w.y * w.y;
        sq.z += v.z * v.z + w.z * w.z; sq.w += v.w * v.w + w.w * w.w;
        row += stride;
    }
    s_sum[tid][0] = sum.x; s_sum[tid][1] = sum.y; s_sum[tid][2] = sum.z; s_sum[tid][3] = sum.w;
    s_sq [tid][0] = sq.x;  s_sq [tid][1] = sq.y;  s_sq [tid][2] = sq.z;  s_sq [tid][3] = sq.w;
    __syncthreads();
    for (int off = 128; off >= 32; off >>= 1) {
        if (tid < off) {
            #pragma unroll
            for (int j = 0; j < 4; ++j) {
                s_sum[tid][j] += s_sum[tid + off][j];
                s_sq [tid][j] += s_sq [tid + off][j];
            }
        }
        __syncthreads();
    }
    if (tid < 32) {
        #pragma unroll
        for (int j = 0; j < 4; ++j) {
            g_psum[blockIdx.x * 128 + tid * 4 + j] = s_sum[tid][j];
            g_psq [blockIdx.x * 128 + tid * 4 + j] = s_sq [tid][j];
        }
    }
}

// ---------------------------------------------------------------------------
// Kernel 2: finalize BN affine params. 1 block x 1024 threads over 1MB.
// c4 = tid&31 (4 channels via float4), s = tid>>5 (32 slices of blocks)
// ---------------------------------------------------------------------------
__global__ void __launch_bounds__(1024) finalize_kernel(const float* __restrict__ gamma,
                                                        const float* __restrict__ beta) {
    __shared__ float r_sum[32][32][4];
    __shared__ float r_sq [32][32][4];
    const int tid = threadIdx.x;
    const int c4 = tid & 31;
    const int s  = tid >> 5;              // 0..31
    const float4* p4 = (const float4*)g_psum;
    const float4* q4 = (const float4*)g_psq;
    float4 S = make_float4(0.f, 0.f, 0.f, 0.f);
    float4 Q = make_float4(0.f, 0.f, 0.f, 0.f);
    #pragma unroll 8
    for (int b = s; b < NBLK_STATS; b += 32) {
        float4 a = p4[b * 32 + c4];
        float4 c = q4[b * 32 + c4];
        S.x += a.x; S.y += a.y; S.z += a.z; S.w += a.w;
        Q.x += c.x; Q.y += c.y; Q.z += c.z; Q.w += c.w;
    }
    r_sum[s][c4][0] = S.x; r_sum[s][c4][1] = S.y; r_sum[s][c4][2] = S.z; r_sum[s][c4][3] = S.w;
    r_sq [s][c4][0] = Q.x; r_sq [s][c4][1] = Q.y; r_sq [s][c4][2] = Q.z; r_sq [s][c4][3] = Q.w;
    __syncthreads();
    if (tid < 32) {
        float S4[4] = {0.f, 0.f, 0.f, 0.f};
        float Q4[4] = {0.f, 0.f, 0.f, 0.f};
        #pragma unroll
        for (int j = 0; j < 32; ++j)
            #pragma unroll
            for (int e = 0; e < 4; ++e) {
                S4[e] += r_sum[j][tid][e];
                Q4[e] += r_sq [j][tid][e];
            }
        const float inv_n = 1.0f / (float)R_TOTAL;
        #pragma unroll
        for (int e = 0; e < 4; ++e) {
            int c = tid * 4 + e;
            float mean = S4[e] * inv_n;
            float var  = Q4[e] * inv_n - mean * mean;
            float sc   = gamma[c] * rsqrtf(var + BN_EPS);
            g_scale[c] = sc;
            g_shift[c] = beta[c] - mean * sc;
        }
    }
}

// ---------------------------------------------------------------------------
// Kernel 3: fused BN-normalize -> QKV (fp16 mma) -> attention -> out-proj
// 256 threads, 2 blocks/SM — R10/R12-verified main (191us), registers
// saturated: DO NOT add live state to this kernel.
// smem: sy16 20KB | qh/kh fp16 21KB each | vv fp32 41KB | small 2KB = ~107KB
// ---------------------------------------------------------------------------
#define QH_BLK   168                        // per-pair q/k stride in halves
#define V_BLK    164                        // per-pair v stride in floats
#define SY_U32   (MT * 8 * 128)             // 5120
#define SMEM_FLOATS (SY_U32 + 2 * (64 * QH_BLK / 2) + 64 * V_BLK + 512)
#define SMEM_BYTES  (SMEM_FLOATS * 4)

__global__ void __launch_bounds__(256, 2)
main_kernel(const float* __restrict__ x,
            const float* __restrict__ b_out,
            const float* __restrict__ mask,
            float* __restrict__ out) {
    extern __shared__ float sm[];
    unsigned* sy16 = (unsigned*)sm;               // [mt][kst][lane^kst][4 regs]
    unsigned short* qh = (unsigned short*)(sm + SY_U32);
    unsigned short* kh = qh + 64 * QH_BLK;
    float* vv      = sm + SY_U32 + (64 * QH_BLK); // after qh+kh (2*168*64 halves)
    float* s_scale = vv + 64 * V_BLK;
    float* s_shift = s_scale + 128;
    float* s_mask  = s_shift + 128;               // mask * log2(e)
    float* s_bout  = s_mask + 128;

    const int tid  = threadIdx.x;
    const int lane = tid & 31;
    const int wrp  = tid >> 5;
    const int tig  = lane & 3;
    const int gid  = lane >> 2;
    const int row0 = blockIdx.x * ROWS;

    if (tid < 128) {
        s_scale[tid] = g_scale[tid];
        s_shift[tid] = g_shift[tid];
        s_bout [tid] = b_out[tid];
    }
    if (tid < 100) s_mask[tid] = mask[tid] * 1.44269504f;  // fold log2e for ex2
    __syncthreads();

    // ---- Phase 1: load + BN-normalize x into fp16 A-fragment sy (no pad) ---
    {
        const float4* x4  = (const float4*)x;
        const float4* sc4 = (const float4*)s_scale;
        const float4* sh4 = (const float4*)s_shift;
        #pragma unroll
        for (int f = tid; f < MT * 16 * 32; f += 256) {
            int r = f >> 5, c4 = f & 31;
            float4 v = x4[(size_t)(row0 + r) * 32 + c4];
            float4 sc = sc4[c4], sh = sh4[c4];
            float e0 = fmaf(v.x, sc.x, sh.x);
            float e1 = fmaf(v.y, sc.y, sh.y);
            float e2 = fmaf(v.z, sc.z, sh.z);
            float e3 = fmaf(v.w, sc.w, sh.w);
            int m = r >> 4, rr = r & 15;
            int g = rr & 7, rbit = rr >> 3;
            int kst = c4 >> 2;
            int kc  = 4 * (c4 & 3);
            int t   = (kc & 7) >> 1;
            int ri  = rbit + (kc >= 8 ? 2 : 0);
            unsigned* base = sy16 + (m * 8 + kst) * 128;
            base[((g * 4 + t)     ^ kst) * 4 + ri] = pkh2(e0, e1);
            base[((g * 4 + t + 1) ^ kst) * 4 + ri] = pkh2(e2, e3);
        }
    }
    __syncthreads();

    // ---- Phase 2: QKV GEMM, SINGLE pass. Warp w: qk n-tiles {4w..4w+3}
    //      (fp16 accumulators) + v n-tiles {32+2w, 32+2w+1} (fp32 acc)
    {
        unsigned qkacc[MT][4][2];
        float    vacc [MT][2][4];
        #pragma unroll
        for (int m = 0; m < MT; ++m) {
            #pragma unroll
            for (int n = 0; n < 4; ++n) { qkacc[m][n][0] = 0u; qkacc[m][n][1] = 0u; }
            #pragma unroll
            for (int n = 0; n < 2; ++n)
                #pragma unroll
                for (int e = 0; e < 4; ++e) vacc[m][n][e] = 0.f;
        }

        const uint2* gqk = g_wqkv16 + (4 * wrp) * 8 * 32 + lane;
        const uint2* gv  = g_wqkv16 + (32 + 2 * wrp) * 8 * 32 + lane;

        #pragma unroll 2
        for (int kst = 0; kst < 8; ++kst) {
            uint2 bqk[4], bv[2];
            #pragma unroll
            for (int n = 0; n < 4; ++n) bqk[n] = __ldg(gqk + (n * 8 + kst) * 32);
            #pragma unroll
            for (int n = 0; n < 2; ++n) bv[n]  = __ldg(gv  + (n * 8 + kst) * 32);
            const int lx = lane ^ kst;
            #pragma unroll
            for (int m = 0; m < MT; ++m) {
                uint4 a = *(const uint4*)&sy16[(m * 8 + kst) * 128 + lx * 4];
                #pragma unroll
                for (int n = 0; n < 4; ++n)
                    mma_f16acc(qkacc[m][n][0], qkacc[m][n][1],
                               a.x, a.y, a.z, a.w, bqk[n].x, bqk[n].y);
                #pragma unroll
                for (int n = 0; n < 2; ++n)
                    mma_f16(vacc[m][n][0], vacc[m][n][1], vacc[m][n][2], vacc[m][n][3],
                            a.x, a.y, a.z, a.w, bv[n].x, bv[n].y);
            }
        }

        // scatter: q/k half2, v float2
        #pragma unroll
        for (int m = 0; m < MT; ++m) {
            int R0 = m * 16 + gid;
            int li0 = R0 / 10, i0 = R0 - li0 * 10;
            int R1 = R0 + 8;
            int li1 = R1 / 10, i1 = R1 - li1 * 10;
            #pragma unroll
            for (int n = 0; n < 4; ++n) {
                int Cn = (4 * wrp + n) * 8 + 2 * tig;
                int sel = Cn >> 7;
                int cc  = Cn & 127;
                int h   = cc >> 4;
                int dh  = cc & 15;
                unsigned short* dst = sel ? kh : qh;
                *(unsigned*)(dst + (li0 * 8 + h) * QH_BLK + i0 * 16 + dh) = qkacc[m][n][0];
                *(unsigned*)(dst + (li1 * 8 + h) * QH_BLK + i1 * 16 + dh) = qkacc[m][n][1];
            }
            #pragma unroll
            for (int n = 0; n < 2; ++n) {
                int cc = (2 * wrp + n) * 8 + 2 * tig;
                int h  = cc >> 4;
                int dh = cc & 15;
                *(float2*)&vv[(li0 * 8 + h) * V_BLK + i0 * 16 + dh] =
                    make_float2(vacc[m][n][0], vacc[m][n][1]);
                *(float2*)&vv[(li1 * 8 + h) * V_BLK + i1 * 16 + dh] =
                    make_float2(vacc[m][n][2], vacc[m][n][3]);
            }
        }
    }
    __syncthreads();

    // ---- Phase 3: masked attention, 4 threads/(item,head), rows sub+{0,4,8}
    //      fp16 dots, ex2 (log2e folded into mask), packed-fp32x2 AV accum.
    {
        const int pair = tid >> 2;          // 0..63 == li*8+h
        const int sub  = tid & 3;
        const int li = pair >> 3;
        const int h  = pair & 7;
        const unsigned short* qb = qh + pair * QH_BLK;
        const unsigned short* kb = kh + pair * QH_BLK;
        const float* vb = vv + pair * V_BLK;
        const int i0 = sub, i1 = sub + 4;
        const bool has3 = (sub < 2);
        const int i2 = has3 ? sub + 8 : sub;

        uint4 q0a = *(const uint4*)(qb + i0 * 16), q0b = *(const uint4*)(qb + i0 * 16 + 8);
        uint4 q1a = *(const uint4*)(qb + i1 * 16), q1b = *(const uint4*)(qb + i1 * 16 + 8);
        uint4 q2a = *(const uint4*)(qb + i2 * 16), q2b = *(const uint4*)(qb + i2 * 16 + 8);

        float d0[10], d1[10], d2[10];
        float s0 = 0.f, s1 = 0.f, s2 = 0.f;
        #pragma unroll
        for (int j = 0; j < 10; ++j) {
            uint4 ka = *(const uint4*)(kb + j * 16);
            uint4 kq = *(const uint4*)(kb + j * 16 + 8);
            // 0.25 logit scale folded into Wq; log2e folded into s_mask
            float p0 = hdot16(q0a, q0b, ka, kq) * s_mask[i0 * 10 + j];
            float p1 = hdot16(q1a, q1b, ka, kq) * s_mask[i1 * 10 + j];
            float p2 = hdot16(q2a, q2b, ka, kq) * s_mask[i2 * 10 + j];
            d0[j] = ex2f(p0); s0 += d0[j];
            d1[j] = ex2f(p1); s1 += d1[j];
            d2[j] = ex2f(p2); s2 += d2[j];
        }

        unsigned long long o0p[8], o1p[8], o2p[8];
        #pragma unroll
        for (int t = 0; t < 8; ++t) { o0p[t] = 0ull; o1p[t] = 0ull; o2p[t] = 0ull; }
        #pragma unroll
        for (int j = 0; j < 10; ++j) {
            unsigned long long pa0, pa1, pa2;
            BCAST2(pa0, d0[j]);
            BCAST2(pa1, d1[j]);
            BCAST2(pa2, d2[j]);
            const ulonglong2* vp = (const ulonglong2*)(vb + j * 16);
            ulonglong2 w0 = vp[0], w1 = vp[1], w2 = vp[2], w3 = vp[3];
            unsigned long long vr[8] = {w0.x, w0.y, w1.x, w1.y, w2.x, w2.y, w3.x, w3.y};
            #pragma unroll
            for (int t = 0; t < 8; ++t) {
                FMA2(o0p[t], pa0, vr[t]);
                FMA2(o1p[t], pa1, vr[t]);
                FMA2(o2p[t], pa2, vr[t]);
            }
        }
        // normalize by 1/sum (packed, rcp.approx)
        {
            unsigned long long pi0, pi1, pi2;
            BCAST2(pi0, rcpf(s0));
            BCAST2(pi1, rcpf(s1));
            BCAST2(pi2, rcpf(s2));
            #pragma unroll
            for (int t = 0; t < 8; ++t) {
                MUL2(o0p[t], pi0);
                MUL2(o1p[t], pi1);
                MUL2(o2p[t], pi2);
            }
        }

        // scatter rows as fp16 fragments: channels h*16+c -> tile (m, kst=h)
        #pragma unroll
        for (int rep = 0; rep < 3; ++rep) {
            if (rep == 2 && !has3) break;
            const unsigned long long* o = rep == 0 ? o0p : (rep == 1 ? o1p : o2p);
            int i = rep == 0 ? i0 : (rep == 1 ? i1 : i2);
            int R = li * 10 + i;
            int m = R >> 4, rr = R & 15;
            int g = rr & 7, rbit = rr >> 3;
            unsigned* base = sy16 + (m * 8 + h) * 128;
            #pragma unroll
            for (int t = 0; t < 4; ++t) {
                int ln = ((g * 4 + t) ^ h) * 4;
                float lo, hi, lo2, hi2;
                UNPK2(lo, hi, o[t]);
                UNPK2(lo2, hi2, o[t + 4]);
                base[ln + rbit]     = pkh2(lo, hi);
                base[ln + rbit + 2] = pkh2(lo2, hi2);
            }
        }
    }
    __syncthreads();

    // ---- Phase 4: out projection, all 8 warps, 2 n-tiles each (fp32 acc) ---
    {
        float acc[MT][2][4];
        #pragma unroll
        for (int m = 0; m < MT; ++m)
            #pragma unroll
            for (int n = 0; n < 2; ++n)
                #pragma unroll
                for (int e = 0; e < 4; ++e) acc[m][n][e] = 0.f;

        const int nt0 = 2 * wrp;
        const uint2* gwp = g_wout16 + nt0 * 8 * 32 + lane;

        #pragma unroll 4
        for (int kst = 0; kst < 8; ++kst) {
            uint2 b[2];
            #pragma unroll
            for (int n = 0; n < 2; ++n)
                b[n] = __ldg(gwp + (n * 8 + kst) * 32);
            const int lx = lane ^ kst;
            #pragma unroll
            for (int m = 0; m < MT; ++m) {
                uint4 a = *(const uint4*)&sy16[(m * 8 + kst) * 128 + lx * 4];
                #pragma unroll
                for (int n = 0; n < 2; ++n)
                    mma_f16(acc[m][n][0], acc[m][n][1], acc[m][n][2], acc[m][n][3],
                            a.x, a.y, a.z, a.w, b[n].x, b[n].y);
            }
        }

        #pragma unroll
        for (int m = 0; m < MT; ++m)
            #pragma unroll
            for (int n = 0; n < 2; ++n) {
                int col = (nt0 + n) * 8 + 2 * tig;
                float b0 = s_bout[col], b1 = s_bout[col + 1];
                int R0 = m * 16 + gid;
                *(float2*)&out[(size_t)(row0 + R0) * 128 + col] =
                    make_float2(acc[m][n][0] + b0, acc[m][n][1] + b1);
                *(float2*)&out[(size_t)(row0 + R0 + 8) * 128 + col] =
                    make_float2(acc[m][n][2] + b0, acc[m][n][3] + b1);
            }
    }
}

// ---------------------------------------------------------------------------
extern "C" void kernel_launch(void* const* d_in, const int* in_sizes, int n_in,
                              void* d_out, int out_size) {
    const float* x     = (const float*)d_in[0];
    const float* gamma = (const float*)d_in[1];
    const float* beta  = (const float*)d_in[2];
    const float* w_qkv = (const float*)d_in[3];
    const float* w_out = (const float*)d_in[4];
    const float* b_out = (const float*)d_in[5];
    const float* mask  = (const float*)d_in[6];
    float* out = (float*)d_out;

    cudaFuncSetAttribute(main_kernel,
                         cudaFuncAttributeMaxDynamicSharedMemorySize, SMEM_BYTES);

    front_kernel<<<NBLK_STATS + NBLK_PERM, 256>>>((const float4*)x, w_qkv, w_out);
    finalize_kernel<<<1, 1024>>>(gamma, beta);
    main_kernel<<<BTOT / NB, 256, SMEM_BYTES>>>(x, b_out, mask, out);
}